// round 3
// baseline (speedup 1.0000x reference)
#include <cuda_runtime.h>
#include <math.h>

#define T_SEQ 4096
#define NF    2048
#define HID   1024
#define G4    4096      // 4*HID gate rows per direction
#define NC_DIR 74       // CTAs per direction in recurrence
#define NCTA  (2*NC_DIR)
#define NTAGS 10
#define START_TAG 8
#define STOP_TAG  9

// Maximum hidden units per CTA = ceil(1024/74) = 14 -> 56 weight rows
#define MAX_ROWS 56
#define REC_SMEM ((MAX_ROWS*1024 + 64 + 16) * 4)   // 229,696 B <= 232,448 opt-in

// ---------------- scratch (device globals: allocation-free rule) -------------
__device__ __align__(16) float g_xp[2][(size_t)T_SEQ * G4];   // 128 MB
__device__ __align__(16) float g_hs[(size_t)T_SEQ * 2048];    // 32 MB  [t][0:1024]=h_f, [1024:2048]=h_b
__device__ __align__(16) float g_feats[T_SEQ * NTAGS];
__device__ unsigned int g_ctr[2];

// ---------------- helpers ----------------------------------------------------
__device__ __forceinline__ unsigned int ld_acquire_u32(const unsigned int* p) {
    unsigned int v;
    asm volatile("ld.acquire.gpu.u32 %0, [%1];" : "=r"(v) : "l"(p) : "memory");
    return v;
}
__device__ __forceinline__ float sigf(float x) { return 1.0f / (1.0f + expf(-x)); }

// ---------------- reset counters (deterministic across graph replays) --------
__global__ void init_kernel() { g_ctr[0] = 0u; g_ctr[1] = 0u; }

// ---------------- input projection GEMM: xp[d][t][g] = x[t]·W_ih_d[g] + b_d[g]
// A: [4096 x 2048] K-major, B: [4096 x 2048] K-major (NT gemm). 128x128x16 tile.
__global__ void __launch_bounds__(256, 2) xp_gemm_kernel(
    const float* __restrict__ A,
    const float* __restrict__ Wf, const float* __restrict__ Wb,
    const float* __restrict__ bf, const float* __restrict__ bb)
{
    __shared__ float As[16][128];
    __shared__ float Bs[16][128];

    const int dir = blockIdx.z;
    const float* __restrict__ B    = dir ? Wb : Wf;
    const float* __restrict__ bias = dir ? bb : bf;
    float* __restrict__ C = g_xp[dir];

    const int tid = threadIdx.x;
    const int tx = tid & 15, ty = tid >> 4;
    const int m0 = blockIdx.y * 128, n0 = blockIdx.x * 128;
    const int lr = tid >> 2;            // 0..63
    const int lc = (tid & 3) * 4;       // 0,4,8,12

    float acc[8][8];
#pragma unroll
    for (int i = 0; i < 8; i++)
#pragma unroll
        for (int j = 0; j < 8; j++) acc[i][j] = 0.0f;

    for (int k0 = 0; k0 < NF; k0 += 16) {
        float4 a0 = *reinterpret_cast<const float4*>(&A[(size_t)(m0 + lr)      * NF + k0 + lc]);
        float4 a1 = *reinterpret_cast<const float4*>(&A[(size_t)(m0 + lr + 64) * NF + k0 + lc]);
        float4 b0 = *reinterpret_cast<const float4*>(&B[(size_t)(n0 + lr)      * NF + k0 + lc]);
        float4 b1 = *reinterpret_cast<const float4*>(&B[(size_t)(n0 + lr + 64) * NF + k0 + lc]);
        __syncthreads();
        As[lc + 0][lr] = a0.x; As[lc + 1][lr] = a0.y; As[lc + 2][lr] = a0.z; As[lc + 3][lr] = a0.w;
        As[lc + 0][lr + 64] = a1.x; As[lc + 1][lr + 64] = a1.y; As[lc + 2][lr + 64] = a1.z; As[lc + 3][lr + 64] = a1.w;
        Bs[lc + 0][lr] = b0.x; Bs[lc + 1][lr] = b0.y; Bs[lc + 2][lr] = b0.z; Bs[lc + 3][lr] = b0.w;
        Bs[lc + 0][lr + 64] = b1.x; Bs[lc + 1][lr + 64] = b1.y; Bs[lc + 2][lr + 64] = b1.z; Bs[lc + 3][lr + 64] = b1.w;
        __syncthreads();
#pragma unroll
        for (int k = 0; k < 16; k++) {
            float af[8], bfr[8];
#pragma unroll
            for (int i = 0; i < 8; i++) af[i] = As[k][ty * 8 + i];
#pragma unroll
            for (int j = 0; j < 8; j++) bfr[j] = Bs[k][tx * 8 + j];
#pragma unroll
            for (int i = 0; i < 8; i++)
#pragma unroll
                for (int j = 0; j < 8; j++) acc[i][j] += af[i] * bfr[j];
        }
    }

#pragma unroll
    for (int i = 0; i < 8; i++) {
        size_t row = (size_t)(m0 + ty * 8 + i) * G4 + n0 + tx * 8;
#pragma unroll
        for (int j = 0; j < 8; j++)
            C[row + j] = acc[i][j] + bias[n0 + tx * 8 + j];
    }
}

// ---------------- persistent recurrence kernel -------------------------------
// blocks 0..73  : forward direction, t = 0..4095
// blocks 74..147: backward direction, t = 4095..0
// W_hh slice lives in SMEM for the whole kernel; cross-CTA step barrier via
// monotonic arrival counter (one per direction).
__global__ void __launch_bounds__(256, 1) lstm_rec_kernel(
    const float* __restrict__ Whf, const float* __restrict__ Whb)
{
    extern __shared__ float smem[];
    float* ws = smem;                   // [R][1024] weight rows
    float* gv = smem + MAX_ROWS * 1024; // [64] reduced gate dot products
    float* cs = gv + 64;                // [16] cell state

    const int blk = blockIdx.x;
    const int dir = blk / NC_DIR;
    const int r   = blk % NC_DIR;
    const int h0 = (r * HID) / NC_DIR;
    const int h1 = ((r + 1) * HID) / NC_DIR;
    const int nh = h1 - h0;             // 13 or 14
    const int R  = 4 * nh;

    const float* __restrict__ W = dir ? Whb : Whf;
    const int tid = threadIdx.x;
    const int lane = tid & 31, warp = tid >> 5;

    // Stage this CTA's W_hh rows (gates i,f,g,o for hidden units [h0,h1)) into SMEM.
    const int nvec = R * 256;  // float4 count
    for (int idx = tid; idx < nvec; idx += 256) {
        int row = idx >> 8;
        int c4  = (idx & 255) * 4;
        int gate = row / nh;
        int j = row - gate * nh;
        float4 v = *reinterpret_cast<const float4*>(&W[(size_t)(gate * HID + h0 + j) * HID + c4]);
        *reinterpret_cast<float4*>(&ws[(size_t)row * HID + c4]) = v;
    }
    if (tid < nh) cs[tid] = 0.0f;
    __syncthreads();

    unsigned int* ctr = &g_ctr[dir];

    for (int step = 0; step < T_SEQ; ++step) {
        const int t = dir ? (T_SEQ - 1 - step) : step;

        // Prefetch xp[t] for this CTA's 4 gate rows (independent of h_prev,
        // overlaps the barrier wait below).
        float xi = 0.f, xf = 0.f, xg = 0.f, xo = 0.f;
        if (tid < nh) {
            const float* xp = &g_xp[dir][(size_t)t * G4];
            xi = __ldg(&xp[h0 + tid]);
            xf = __ldg(&xp[HID + h0 + tid]);
            xg = __ldg(&xp[2 * HID + h0 + tid]);
            xo = __ldg(&xp[3 * HID + h0 + tid]);
        }

        if (step > 0) {
            if (tid == 0) {
                const unsigned int target = (unsigned int)(NC_DIR * step);
                while (ld_acquire_u32(ctr) < target) { }
            }
            __syncthreads();

            // Load h_prev (1024 fp32) — L2 only (other SMs produced it).
            const float* hp = &g_hs[(size_t)(dir ? t + 1 : t - 1) * 2048 + dir * HID];
            float4 hreg[8];
#pragma unroll
            for (int k = 0; k < 8; k++)
                hreg[k] = __ldcg(reinterpret_cast<const float4*>(hp + 4 * lane + 128 * k));

            // Each warp computes rows rl = warp, warp+8, ... (<= 7 rows).
            for (int rl = warp; rl < R; rl += 8) {
                const float* wr = &ws[(size_t)rl * HID];
                float a0 = 0.f, a1 = 0.f, a2 = 0.f, a3 = 0.f;
#pragma unroll
                for (int k = 0; k < 8; k++) {
                    float4 w = *reinterpret_cast<const float4*>(wr + 4 * lane + 128 * k);
                    a0 += w.x * hreg[k].x;
                    a1 += w.y * hreg[k].y;
                    a2 += w.z * hreg[k].z;
                    a3 += w.w * hreg[k].w;
                }
                float a = (a0 + a1) + (a2 + a3);
#pragma unroll
                for (int off = 16; off > 0; off >>= 1)
                    a += __shfl_xor_sync(0xffffffffu, a, off);
                if (lane == 0) gv[rl] = a;
            }
        } else {
            if (tid < 64) gv[tid] = 0.0f;
        }
        __syncthreads();

        // Gate nonlinearity + state update for this CTA's hidden units.
        if (tid < nh) {
            int j = tid;
            float gi = gv[j]          + xi;
            float gf = gv[nh + j]     + xf;
            float gg = gv[2 * nh + j] + xg;
            float go = gv[3 * nh + j] + xo;
            float c = sigf(gf) * cs[j] + sigf(gi) * tanhf(gg);
            cs[j] = c;
            float h = sigf(go) * tanhf(c);
            g_hs[(size_t)t * 2048 + dir * HID + h0 + j] = h;
        }
        __threadfence();
        __syncthreads();
        if (tid == 0) atomicAdd(ctr, 1u);
    }
}

// ---------------- feats: [4096 x 10] = hs @ W_lin^T + b ----------------------
__global__ void feats_kernel(const float* __restrict__ Wlin, const float* __restrict__ blin)
{
    const int t = blockIdx.x;
    const int warp = threadIdx.x >> 5;   // 10 warps = 10 tags
    const int lane = threadIdx.x & 31;
    const float* h = &g_hs[(size_t)t * 2048];
    const float* w = &Wlin[(size_t)warp * 2048];
    float a0 = 0.f, a1 = 0.f, a2 = 0.f, a3 = 0.f;
#pragma unroll
    for (int k = 0; k < 16; k++) {
        float4 hv = *reinterpret_cast<const float4*>(h + 4 * lane + 128 * k);
        float4 wv = __ldg(reinterpret_cast<const float4*>(w + 4 * lane + 128 * k));
        a0 += hv.x * wv.x; a1 += hv.y * wv.y; a2 += hv.z * wv.z; a3 += hv.w * wv.w;
    }
    float a = (a0 + a1) + (a2 + a3);
#pragma unroll
    for (int off = 16; off > 0; off >>= 1)
        a += __shfl_xor_sync(0xffffffffu, a, off);
    if (lane == 0) g_feats[t * NTAGS + warp] = a + blin[warp];
}

// ---------------- Viterbi decode (single warp, register-resident) ------------
__global__ void viterbi_kernel(const float* __restrict__ trans, float* __restrict__ out)
{
    __shared__ unsigned char bps[T_SEQ * NTAGS];  // 40 KB backpointers
    __shared__ unsigned char path[T_SEQ];

    const int lane = threadIdx.x;
    float trow[NTAGS];
    float fv;
    if (lane < NTAGS) {
#pragma unroll
        for (int i = 0; i < NTAGS; i++) trow[i] = trans[lane * NTAGS + i];
        fv = (lane == START_TAG) ? 0.0f : -10000.0f;
    } else {
#pragma unroll
        for (int i = 0; i < NTAGS; i++) trow[i] = 0.0f;
        fv = -1e30f;
    }

    for (int t = 0; t < T_SEQ; t++) {
        float feat = (lane < NTAGS) ? g_feats[t * NTAGS + lane] : 0.0f;
        float best = -3.0e38f; int bi = 0;
#pragma unroll
        for (int i = 0; i < NTAGS; i++) {
            float v = __shfl_sync(0xffffffffu, fv, i) + trow[i];
            if (v > best) { best = v; bi = i; }   // strict > => first-index tie rule
        }
        if (lane < NTAGS) bps[t * NTAGS + lane] = (unsigned char)bi;
        fv = best + feat;
    }

    float term = (lane < NTAGS) ? (fv + trans[STOP_TAG * NTAGS + lane]) : -3.0e38f;
    float bsc = -3.0e38f; int bidx = 0;
#pragma unroll
    for (int i = 0; i < NTAGS; i++) {
        float v = __shfl_sync(0xffffffffu, term, i);
        if (v > bsc) { bsc = v; bidx = i; }
    }

    if (lane == 0) {
        out[0] = bsc;
        int cur = bidx;
        path[T_SEQ - 1] = (unsigned char)cur;
        for (int t = T_SEQ - 2; t >= 0; --t) {
            cur = bps[(t + 1) * NTAGS + cur];
            path[t] = (unsigned char)cur;
        }
    }
    __syncthreads();
    for (int t = lane; t < T_SEQ; t += 32) out[1 + t] = (float)path[t];
}

// ---------------- launch ------------------------------------------------------
extern "C" void kernel_launch(void* const* d_in, const int* in_sizes, int n_in,
                              void* d_out, int out_size)
{
    const float* sentence = (const float*)d_in[0];
    const float* W_ih_f   = (const float*)d_in[1];
    const float* W_hh_f   = (const float*)d_in[2];
    /* b_f folded into xp via gemm bias */
    const float* b_f      = (const float*)d_in[3];
    const float* W_ih_b   = (const float*)d_in[4];
    const float* W_hh_b   = (const float*)d_in[5];
    const float* b_b      = (const float*)d_in[6];
    const float* W_lin    = (const float*)d_in[7];
    const float* b_lin    = (const float*)d_in[8];
    const float* trans    = (const float*)d_in[9];
    float* out = (float*)d_out;

    cudaFuncSetAttribute((const void*)lstm_rec_kernel,
                         cudaFuncAttributeMaxDynamicSharedMemorySize, REC_SMEM);

    init_kernel<<<1, 1>>>();

    dim3 gg(G4 / 128, T_SEQ / 128, 2);
    xp_gemm_kernel<<<gg, 256>>>(sentence, W_ih_f, W_ih_b, b_f, b_b);

    lstm_rec_kernel<<<NCTA, 256, REC_SMEM>>>(W_hh_f, W_hh_b);

    feats_kernel<<<T_SEQ, NTAGS * 32>>>(W_lin, b_lin);

    viterbi_kernel<<<1, 32>>>(trans, out);

    (void)in_sizes; (void)n_in; (void)out_size;
}

// round 4
// speedup vs baseline: 1.3595x; 1.3595x over previous
#include <cuda_runtime.h>
#include <math.h>

#define T_SEQ 4096
#define NF    2048
#define HID   1024
#define G4    4096      // 4*HID gate rows per direction
#define NC_DIR 74       // CTAs per direction in recurrence
#define NCTA  (2*NC_DIR)
#define NTAGS 10
#define START_TAG 8
#define STOP_TAG  9

// Recurrence layout: up to 14 hidden units/CTA -> 56 gate rows.
// Per warp: 7 rows (stride 8). Rows i=0..3 register-resident, i=4..6 in SMEM.
#define RPW       7
#define REG_ROWS  4
#define SMEM_ROWS 24                      // rows 32..55
// Pad to 128KB so at most 1 CTA/SM can be resident (co-residency invariant).
#define REC_SMEM  (128 * 1024)

// ---------------- scratch (device globals: allocation-free rule) -------------
__device__ __align__(16) float g_xp[2][(size_t)T_SEQ * G4];   // 128 MB
__device__ __align__(16) float g_hs[(size_t)T_SEQ * 2048];    // 32 MB
__device__ __align__(16) float g_feats[T_SEQ * NTAGS];
__device__ unsigned int g_ctr[2];

// ---------------- helpers ----------------------------------------------------
__device__ __forceinline__ unsigned int ld_acquire_u32(const unsigned int* p) {
    unsigned int v;
    asm volatile("ld.acquire.gpu.u32 %0, [%1];" : "=r"(v) : "l"(p) : "memory");
    return v;
}
__device__ __forceinline__ void red_release_add(unsigned int* p, unsigned int v) {
    asm volatile("red.release.gpu.global.add.u32 [%0], %1;" :: "l"(p), "r"(v) : "memory");
}
__device__ __forceinline__ float sigf(float x) { return 1.0f / (1.0f + expf(-x)); }

// ---------------- reset counters ---------------------------------------------
__global__ void init_kernel() { g_ctr[0] = 0u; g_ctr[1] = 0u; }

// ---------------- input projection GEMM: xp[d][t][g] = x[t]·W_ih_d[g] + b ----
__global__ void __launch_bounds__(256, 2) xp_gemm_kernel(
    const float* __restrict__ A,
    const float* __restrict__ Wf, const float* __restrict__ Wb,
    const float* __restrict__ bf, const float* __restrict__ bb)
{
    __shared__ float As[16][128];
    __shared__ float Bs[16][128];

    const int dir = blockIdx.z;
    const float* __restrict__ B    = dir ? Wb : Wf;
    const float* __restrict__ bias = dir ? bb : bf;
    float* __restrict__ C = g_xp[dir];

    const int tid = threadIdx.x;
    const int tx = tid & 15, ty = tid >> 4;
    const int m0 = blockIdx.y * 128, n0 = blockIdx.x * 128;
    const int lr = tid >> 2;
    const int lc = (tid & 3) * 4;

    float acc[8][8];
#pragma unroll
    for (int i = 0; i < 8; i++)
#pragma unroll
        for (int j = 0; j < 8; j++) acc[i][j] = 0.0f;

    for (int k0 = 0; k0 < NF; k0 += 16) {
        float4 a0 = *reinterpret_cast<const float4*>(&A[(size_t)(m0 + lr)      * NF + k0 + lc]);
        float4 a1 = *reinterpret_cast<const float4*>(&A[(size_t)(m0 + lr + 64) * NF + k0 + lc]);
        float4 b0 = *reinterpret_cast<const float4*>(&B[(size_t)(n0 + lr)      * NF + k0 + lc]);
        float4 b1 = *reinterpret_cast<const float4*>(&B[(size_t)(n0 + lr + 64) * NF + k0 + lc]);
        __syncthreads();
        As[lc + 0][lr] = a0.x; As[lc + 1][lr] = a0.y; As[lc + 2][lr] = a0.z; As[lc + 3][lr] = a0.w;
        As[lc + 0][lr + 64] = a1.x; As[lc + 1][lr + 64] = a1.y; As[lc + 2][lr + 64] = a1.z; As[lc + 3][lr + 64] = a1.w;
        Bs[lc + 0][lr] = b0.x; Bs[lc + 1][lr] = b0.y; Bs[lc + 2][lr] = b0.z; Bs[lc + 3][lr] = b0.w;
        Bs[lc + 0][lr + 64] = b1.x; Bs[lc + 1][lr + 64] = b1.y; Bs[lc + 2][lr + 64] = b1.z; Bs[lc + 3][lr + 64] = b1.w;
        __syncthreads();
#pragma unroll
        for (int k = 0; k < 16; k++) {
            float af[8], bfr[8];
#pragma unroll
            for (int i = 0; i < 8; i++) af[i] = As[k][ty * 8 + i];
#pragma unroll
            for (int j = 0; j < 8; j++) bfr[j] = Bs[k][tx * 8 + j];
#pragma unroll
            for (int i = 0; i < 8; i++)
#pragma unroll
                for (int j = 0; j < 8; j++) acc[i][j] += af[i] * bfr[j];
        }
    }

#pragma unroll
    for (int i = 0; i < 8; i++) {
        size_t row = (size_t)(m0 + ty * 8 + i) * G4 + n0 + tx * 8;
#pragma unroll
        for (int j = 0; j < 8; j++)
            C[row + j] = acc[i][j] + bias[n0 + tx * 8 + j];
    }
}

// ---------------- persistent recurrence kernel -------------------------------
// blocks 0..73: forward; 74..147: backward. W_hh slice split between registers
// (4 rows/warp) and SMEM (3 rows/warp). Step barrier = red.release counter +
// ld.acquire polling (no ATOMG returns, no per-thread MEMBAR).
__global__ void __launch_bounds__(256, 1) lstm_rec_kernel(
    const float* __restrict__ Whf, const float* __restrict__ Whb)
{
    extern __shared__ float smem[];
    float* ws = smem;                          // [SMEM_ROWS][1024]
    float* gv = smem + SMEM_ROWS * 1024;       // [64] gate dot products
    float* cs = gv + 64;                       // [16] cell state

    const int blk = blockIdx.x;
    const int dir = blk / NC_DIR;
    const int r   = blk % NC_DIR;
    const int h0 = (r * HID) / NC_DIR;
    const int h1 = ((r + 1) * HID) / NC_DIR;
    const int nh = h1 - h0;                    // 13 or 14
    const int R  = 4 * nh;

    const float* __restrict__ W = dir ? Whb : Whf;
    const int tid = threadIdx.x;
    const int lane = tid & 31, warp = tid >> 5;

    // --- register-resident weight rows: rl = warp + 8*i, i=0..3 --------------
    float4 wreg[REG_ROWS][8];
#pragma unroll
    for (int i = 0; i < REG_ROWS; i++) {
        int rl = warp + 8 * i;
        int gate = rl / nh;
        int j = rl - gate * nh;
        const float* wr = (rl < R) ? &W[(size_t)(gate * HID + h0 + j) * HID] : W;
#pragma unroll
        for (int k = 0; k < 8; k++)
            wreg[i][k] = *reinterpret_cast<const float4*>(wr + 4 * lane + 128 * k);
    }

    // --- SMEM weight rows: rl = 32..55 ---------------------------------------
    for (int idx = tid; idx < SMEM_ROWS * 256; idx += 256) {
        int rl = 32 + (idx >> 8);
        int c4 = (idx & 255) * 4;
        int gate = rl / nh;
        int j = rl - gate * nh;
        const float* wr = (rl < R) ? &W[(size_t)(gate * HID + h0 + j) * HID] : W;
        *reinterpret_cast<float4*>(&ws[(size_t)(rl - 32) * HID + c4]) =
            *reinterpret_cast<const float4*>(wr + c4);
    }
    if (tid < nh) cs[tid] = 0.0f;
    __syncthreads();

    unsigned int* ctr = &g_ctr[dir];

    for (int step = 0; step < T_SEQ; ++step) {
        const int t = dir ? (T_SEQ - 1 - step) : step;

        // Prefetch xp[t] for this CTA's gate rows (independent of h_prev).
        float xi = 0.f, xf = 0.f, xg = 0.f, xo = 0.f;
        if (tid < nh) {
            const float* xp = &g_xp[dir][(size_t)t * G4];
            xi = __ldg(&xp[h0 + tid]);
            xf = __ldg(&xp[HID + h0 + tid]);
            xg = __ldg(&xp[2 * HID + h0 + tid]);
            xo = __ldg(&xp[3 * HID + h0 + tid]);
        }

        if (step > 0) {
            if (tid == 0) {
                const unsigned int target = (unsigned int)(NC_DIR * step);
                while (ld_acquire_u32(ctr) < target) { }
            }
            __syncthreads();

            // h_prev (1024 fp32) from L2 (other SMs wrote it).
            const float* hp = &g_hs[(size_t)(dir ? t + 1 : t - 1) * 2048 + dir * HID];
            float4 hreg[8];
#pragma unroll
            for (int k = 0; k < 8; k++)
                hreg[k] = __ldcg(reinterpret_cast<const float4*>(hp + 4 * lane + 128 * k));

            float a[RPW];
            // register rows
#pragma unroll
            for (int i = 0; i < REG_ROWS; i++) {
                float a0 = 0.f, a1 = 0.f, a2 = 0.f, a3 = 0.f;
#pragma unroll
                for (int k = 0; k < 8; k++) {
                    a0 += wreg[i][k].x * hreg[k].x;
                    a1 += wreg[i][k].y * hreg[k].y;
                    a2 += wreg[i][k].z * hreg[k].z;
                    a3 += wreg[i][k].w * hreg[k].w;
                }
                a[i] = (a0 + a1) + (a2 + a3);
            }
            // SMEM rows
#pragma unroll
            for (int i = REG_ROWS; i < RPW; i++) {
                const float* wr = &ws[(size_t)(warp + 8 * i - 32) * HID];
                float a0 = 0.f, a1 = 0.f, a2 = 0.f, a3 = 0.f;
#pragma unroll
                for (int k = 0; k < 8; k++) {
                    float4 w = *reinterpret_cast<const float4*>(wr + 4 * lane + 128 * k);
                    a0 += w.x * hreg[k].x;
                    a1 += w.y * hreg[k].y;
                    a2 += w.z * hreg[k].z;
                    a3 += w.w * hreg[k].w;
                }
                a[i] = (a0 + a1) + (a2 + a3);
            }
            // independent shuffle-reduce chains (pipelined)
#pragma unroll
            for (int off = 16; off > 0; off >>= 1)
#pragma unroll
                for (int i = 0; i < RPW; i++)
                    a[i] += __shfl_xor_sync(0xffffffffu, a[i], off);
            if (lane == 0) {
#pragma unroll
                for (int i = 0; i < RPW; i++) gv[warp + 8 * i] = a[i];
            }
        } else {
            if (tid < 64) gv[tid] = 0.0f;
        }
        __syncthreads();

        // Gate nonlinearity + state update.
        if (tid < nh) {
            int j = tid;
            float gi = gv[j]          + xi;
            float gf = gv[nh + j]     + xf;
            float gg = gv[2 * nh + j] + xg;
            float go = gv[3 * nh + j] + xo;
            float c = sigf(gf) * cs[j] + sigf(gi) * tanhf(gg);
            cs[j] = c;
            float h = sigf(go) * tanhf(c);
            g_hs[(size_t)t * 2048 + dir * HID + h0 + j] = h;
        }
        __syncthreads();                 // all h stores happen-before tid0's release
        if (tid == 0) red_release_add(ctr, 1u);
    }
}

// ---------------- feats: [4096 x 10] = hs @ W_lin^T + b ----------------------
__global__ void feats_kernel(const float* __restrict__ Wlin, const float* __restrict__ blin)
{
    const int t = blockIdx.x;
    const int warp = threadIdx.x >> 5;
    const int lane = threadIdx.x & 31;
    const float* h = &g_hs[(size_t)t * 2048];
    const float* w = &Wlin[(size_t)warp * 2048];
    float a0 = 0.f, a1 = 0.f, a2 = 0.f, a3 = 0.f;
#pragma unroll
    for (int k = 0; k < 16; k++) {
        float4 hv = *reinterpret_cast<const float4*>(h + 4 * lane + 128 * k);
        float4 wv = __ldg(reinterpret_cast<const float4*>(w + 4 * lane + 128 * k));
        a0 += hv.x * wv.x; a1 += hv.y * wv.y; a2 += hv.z * wv.z; a3 += hv.w * wv.w;
    }
    float a = (a0 + a1) + (a2 + a3);
#pragma unroll
    for (int off = 16; off > 0; off >>= 1)
        a += __shfl_xor_sync(0xffffffffu, a, off);
    if (lane == 0) g_feats[t * NTAGS + warp] = a + blin[warp];
}

// ---------------- Viterbi decode (single warp, register-resident) ------------
__global__ void viterbi_kernel(const float* __restrict__ trans, float* __restrict__ out)
{
    __shared__ unsigned char bps[T_SEQ * NTAGS];
    __shared__ unsigned char path[T_SEQ];

    const int lane = threadIdx.x;
    float trow[NTAGS];
    float fv;
    if (lane < NTAGS) {
#pragma unroll
        for (int i = 0; i < NTAGS; i++) trow[i] = trans[lane * NTAGS + i];
        fv = (lane == START_TAG) ? 0.0f : -10000.0f;
    } else {
#pragma unroll
        for (int i = 0; i < NTAGS; i++) trow[i] = 0.0f;
        fv = -1e30f;
    }

    for (int t = 0; t < T_SEQ; t++) {
        float feat = (lane < NTAGS) ? g_feats[t * NTAGS + lane] : 0.0f;
        float best = -3.0e38f; int bi = 0;
#pragma unroll
        for (int i = 0; i < NTAGS; i++) {
            float v = __shfl_sync(0xffffffffu, fv, i) + trow[i];
            if (v > best) { best = v; bi = i; }
        }
        if (lane < NTAGS) bps[t * NTAGS + lane] = (unsigned char)bi;
        fv = best + feat;
    }

    float term = (lane < NTAGS) ? (fv + trans[STOP_TAG * NTAGS + lane]) : -3.0e38f;
    float bsc = -3.0e38f; int bidx = 0;
#pragma unroll
    for (int i = 0; i < NTAGS; i++) {
        float v = __shfl_sync(0xffffffffu, term, i);
        if (v > bsc) { bsc = v; bidx = i; }
    }

    if (lane == 0) {
        out[0] = bsc;
        int cur = bidx;
        path[T_SEQ - 1] = (unsigned char)cur;
        for (int t = T_SEQ - 2; t >= 0; --t) {
            cur = bps[(t + 1) * NTAGS + cur];
            path[t] = (unsigned char)cur;
        }
    }
    __syncthreads();
    for (int t = lane; t < T_SEQ; t += 32) out[1 + t] = (float)path[t];
}

// ---------------- launch ------------------------------------------------------
extern "C" void kernel_launch(void* const* d_in, const int* in_sizes, int n_in,
                              void* d_out, int out_size)
{
    const float* sentence = (const float*)d_in[0];
    const float* W_ih_f   = (const float*)d_in[1];
    const float* W_hh_f   = (const float*)d_in[2];
    const float* b_f      = (const float*)d_in[3];
    const float* W_ih_b   = (const float*)d_in[4];
    const float* W_hh_b   = (const float*)d_in[5];
    const float* b_b      = (const float*)d_in[6];
    const float* W_lin    = (const float*)d_in[7];
    const float* b_lin    = (const float*)d_in[8];
    const float* trans    = (const float*)d_in[9];
    float* out = (float*)d_out;

    cudaFuncSetAttribute((const void*)lstm_rec_kernel,
                         cudaFuncAttributeMaxDynamicSharedMemorySize, REC_SMEM);

    init_kernel<<<1, 1>>>();

    dim3 gg(G4 / 128, T_SEQ / 128, 2);
    xp_gemm_kernel<<<gg, 256>>>(sentence, W_ih_f, W_ih_b, b_f, b_b);

    lstm_rec_kernel<<<NCTA, 256, REC_SMEM>>>(W_hh_f, W_hh_b);

    feats_kernel<<<T_SEQ, NTAGS * 32>>>(W_lin, b_lin);

    viterbi_kernel<<<1, 32>>>(trans, out);

    (void)in_sizes; (void)n_in; (void)out_size;
}